// round 11
// baseline (speedup 1.0000x reference)
#include <cuda_runtime.h>
#include <cuda_bf16.h>
#include <cuda_fp16.h>
#include <cstdint>

#define NN 50000
#define EE 1600000
#define DD 128
#define NB 196          // ceil(NN / 256)
#define NTILES 391      // ceil(NN / 128)

// K1: probe(1) + count + conv + wprep
#define K1_COUNT 3125
#define K1_CONV  12500
#define K1_WPREP 65
#define K1_TOTAL (1 + K1_COUNT + K1_CONV + K1_WPREP)
// K2: scan + fill + zero
#define K2_SCAN  392
#define K2_FILL  3125
#define K2_ZERO  391
#define K2_TOTAL (K2_SCAN + K2_FILL + K2_ZERO)
// K3: agg + gemm + final
#define K3_AGG   12500
#define K3_GEMM  (2 * NTILES)
#define K3_FINAL 6250
#define K3_TOTAL (K3_AGG + K3_GEMM + K3_FINAL)

// ---------------- scratch (device globals; no allocation allowed) ----------
// Zero-initialized at module load. Per-replay invariants:
//   g_cnt/g_desc re-zeroed by K2 zero blocks; g_scan_done reset by K1 blk0;
//   g_agg_done/g_gemm_done reset by K2 blk0; g_i64sig idempotent.
__device__ float2 g_p[NN];
__device__ float2 g_q[NN];
__device__ int g_csr_st[EE];
__device__ int g_csr_s [EE];
__device__ int g_rank_st[EE];
__device__ int g_rank_s [EE];
__device__ int g_cnt_st[NN];
__device__ int g_cnt_s [NN];
__device__ int g_off_st[NN + 1];
__device__ int g_off_s [NN + 1];
__device__ int g_desc[2][NB];
__device__ float g_wl0[DD], g_wl1[DD], g_wr0[DD], g_wr1[DD], g_b2[2];
__device__ int g_i64sig;      // 0=unset, 1=int32, 2=int64
__device__ int g_scan_done;
__device__ int g_agg_done;
__device__ int g_gemm_done;

__device__ __half g_xh[2][NN * DD];
__device__ __nv_bfloat162 g_Ahi[2][NN * 64];
__device__ __nv_bfloat162 g_Alo[2][NN * 64];
__device__ __nv_bfloat162 g_Bhi[2][128 * 128];
__device__ __nv_bfloat162 g_Blo[2][128 * 128];

// ================= helpers ====================================================
__device__ __forceinline__ uint32_t smem_to_u32(const void* p) {
    uint32_t a;
    asm("{ .reg .u64 t; cvta.to.shared.u64 t, %1; cvt.u32.u64 %0, t; }"
        : "=r"(a) : "l"(p));
    return a;
}
__device__ __forceinline__ void ldsm4(uint32_t* r, uint32_t addr) {
    asm volatile("ldmatrix.sync.aligned.m8n8.x4.shared.b16 {%0,%1,%2,%3}, [%4];"
        : "=r"(r[0]), "=r"(r[1]), "=r"(r[2]), "=r"(r[3]) : "r"(addr));
}
__device__ __forceinline__ void mma16816(float* c, const uint32_t* a, const uint32_t* b) {
    asm volatile("mma.sync.aligned.m16n8k16.row.col.f32.bf16.bf16.f32 "
        "{%0,%1,%2,%3}, {%4,%5,%6,%7}, {%8,%9}, {%0,%1,%2,%3};"
        : "+f"(c[0]), "+f"(c[1]), "+f"(c[2]), "+f"(c[3])
        : "r"(a[0]), "r"(a[1]), "r"(a[2]), "r"(a[3]), "r"(b[0]), "r"(b[1]));
}
__device__ __forceinline__ void split_pair(float a, float b,
                                           __nv_bfloat162& hi, __nv_bfloat162& lo)
{
    __nv_bfloat16 ha = __float2bfloat16(a), hb = __float2bfloat16(b);
    hi.x = ha; hi.y = hb;
    lo.x = __float2bfloat16(a - __bfloat162float(ha));
    lo.y = __float2bfloat16(b - __bfloat162float(hb));
}
__device__ __forceinline__ void acc_uint4(float* a, uint4 v)
{
    float2 f0 = __half22float2(*(const __half2*)&v.x);
    float2 f1 = __half22float2(*(const __half2*)&v.y);
    float2 f2 = __half22float2(*(const __half2*)&v.z);
    float2 f3 = __half22float2(*(const __half2*)&v.w);
    a[0] += f0.x; a[1] += f0.y; a[2] += f1.x; a[3] += f1.y;
    a[4] += f2.x; a[5] += f2.y; a[6] += f3.x; a[7] += f3.y;
}
// spin until counter reaches target (thread 0 spins, block-wide release)
__device__ __forceinline__ void block_spin(int* ctr, int target)
{
    if (threadIdx.x == 0) {
        while (atomicAdd(ctr, 0) < target) { }
    }
    __syncthreads();
    __threadfence();
}
// all-threads fence + single increment (call after all stores, all threads)
__device__ __forceinline__ void block_signal(int* ctr)
{
    __threadfence();
    __syncthreads();
    if (threadIdx.x == 0) atomicAdd(ctr, 1);
}

// ===== K1: probe(blk0) + count(spin i64) + conv + wprep ======================
__global__ void __launch_bounds__(256) k_pc(
    const float* __restrict__ x_student, const float* __restrict__ x_studies,
    const int* __restrict__ ei_a, const int* __restrict__ ei_b,
    const float* __restrict__ st_Wl, const float* __restrict__ st_Wr,
    const float* __restrict__ s_Wl,  const float* __restrict__ s_Wr,
    const float* __restrict__ Wl2, const float* __restrict__ b2,
    const float* __restrict__ Wr2, const float* __restrict__ linW,
    const float* __restrict__ linb)
{
    int bx = blockIdx.x;
    int tid = threadIdx.x;

    if (bx == 0) {
        // probe int64/int32 + reset scan counter for this replay
        __shared__ int anz;
        if (tid == 0) { anz = 0; g_scan_done = 0; }
        __syncthreads();
        if (ei_a[2 * tid + 1] != 0) atomicOr(&anz, 1);
        __syncthreads();
        if (tid == 0) {
            __threadfence();
            atomicExch(&g_i64sig, anz ? 1 : 2);
        }
        return;
    }
    if (bx <= K1_COUNT) {
        // histogram + rank capture: 4 edges/thread, int4
        __shared__ int s_sig;
        if (tid == 0) {
            int s;
            do { s = atomicAdd(&g_i64sig, 0); } while (s == 0);
            s_sig = s;
        }
        __syncthreads();
        int i64 = s_sig - 1;
        int t = (bx - 1) * 256 + tid;
        const int* ei; int* cnt; int* rank; int g;
        if (t < EE / 4)      { ei = ei_a; cnt = g_cnt_st; rank = g_rank_st; g = t; }
        else if (t < EE / 2) { ei = ei_b; cnt = g_cnt_s;  rank = g_rank_s;  g = t - EE / 4; }
        else return;
        int d0, d1, d2, d3;
        if (!i64) {
            int4 d = __ldg(&((const int4*)(ei + EE))[g]);
            d0 = d.x; d1 = d.y; d2 = d.z; d3 = d.w;
        } else {
            const int4* p = (const int4*)(ei + 2 * EE);
            int4 a = __ldg(&p[2 * g]), b = __ldg(&p[2 * g + 1]);
            d0 = a.x; d1 = a.z; d2 = b.x; d3 = b.z;
        }
        int4 r = make_int4(0, 0, 0, 0);
        if ((unsigned)d0 < NN) r.x = atomicAdd(&cnt[d0], 1);
        if ((unsigned)d1 < NN) r.y = atomicAdd(&cnt[d1], 1);
        if ((unsigned)d2 < NN) r.z = atomicAdd(&cnt[d2], 1);
        if ((unsigned)d3 < NN) r.w = atomicAdd(&cnt[d3], 1);
        ((int4*)rank)[g] = r;
        return;
    }
    if (bx <= K1_COUNT + K1_CONV) {
        // fp16 gather-table conversion
        int cb = bx - 1 - K1_COUNT;
        int a = cb / 6250;
        int t = (cb % 6250) * 256 + tid;
        if (t >= NN * 32) return;
        const float4* x = (const float4*)(a == 0 ? x_student : x_studies);
        float4 v = x[t];
        uint2 u;
        *(__half2*)&u.x = __floats2half2_rn(v.x, v.y);
        *(__half2*)&u.y = __floats2half2_rn(v.z, v.w);
        ((uint2*)g_xh[a])[t] = u;
        return;
    }
    // weight prep
    int wb = bx - 1 - K1_COUNT - K1_CONV;
    if (wb == 64) {
        int k = tid >> 1, j = tid & 1;
        float sl = 0.f, sr = 0.f;
        for (int m = 0; m < 128; m++) {
            float w = linW[m * 2 + j];
            sl += Wl2[k * 128 + m] * w;
            sr += Wr2[k * 128 + m] * w;
        }
        if (j == 0) { g_wl0[k] = sl; g_wr0[k] = sr; }
        else        { g_wl1[k] = sl; g_wr1[k] = sr; }
        if (k == 0) {
            float sb = 0.f;
            for (int m = 0; m < 128; m++) sb += b2[m] * linW[m * 2 + j];
            g_b2[j] = sb + linb[j];
        }
        return;
    }
    int t = wb * 256 + tid;   // [type][n][k4]
    int k4 = t & 63, n = (t >> 6) & 127, type = t >> 13;
    const float* Wl = type == 0 ? st_Wl : s_Wl;
    const float* Wr = type == 0 ? st_Wr : s_Wr;
    int k = k4 * 4;
    float v[4];
#pragma unroll
    for (int i = 0; i < 4; i++) {
        int kk = k + i;
        v[i] = (kk < 128) ? Wl[kk * 128 + n] : Wr[(kk - 128) * 128 + n];
    }
    __nv_bfloat162 h0, l0, h1, l1;
    split_pair(v[0], v[1], h0, l0);
    split_pair(v[2], v[3], h1, l1);
    int base = n * 128 + k4 * 2;
    g_Bhi[type][base] = h0;     g_Bhi[type][base + 1] = h1;
    g_Blo[type][base] = l0;     g_Blo[type][base + 1] = l1;
}

// ===== K2: scan (blocks 0..391) + fill/zero (spin on scan done) ==============
__global__ void __launch_bounds__(256) k_sf(const int* __restrict__ ei_a,
                                            const int* __restrict__ ei_b)
{
    int bx = blockIdx.x;
    int t = threadIdx.x;

    if (bx < K2_SCAN) {
        if (bx == 0 && t == 0) { g_agg_done = 0; g_gemm_done = 0; }
        int y = bx >= NB;
        int b = bx - y * NB;
        const int* cnt = y ? g_cnt_s : g_cnt_st;
        int* off = y ? g_off_s : g_off_st;
        int i = b * 256 + t;
        int v = (i < NN) ? cnt[i] : 0;
        __shared__ int sh[256];
        sh[t] = v;
        __syncthreads();
#pragma unroll
        for (int o = 1; o < 256; o <<= 1) {
            int u = (t >= o) ? sh[t - o] : 0;
            __syncthreads();
            sh[t] += u;
            __syncthreads();
        }
        int incl = sh[t];
        if (t == 255) atomicExch(&g_desc[y][b], incl + 1);
        int partial = 0;
        if (t < b) {
            int d;
            do { d = atomicAdd(&g_desc[y][t], 0); } while (d == 0);
            partial = d - 1;
        }
        __syncthreads();
        sh[t] = partial;
        __syncthreads();
#pragma unroll
        for (int o = 128; o; o >>= 1) {
            if (t < o) sh[t] += sh[t + o];
            __syncthreads();
        }
        int excl = sh[0] + incl - v;
        if (i < NN) {
            off[i] = excl;
            if (i == NN - 1) off[NN] = excl + v;
        }
        block_signal(&g_scan_done);
        return;
    }

    block_spin(&g_scan_done, K2_SCAN);

    int fb = bx - K2_SCAN;
    if (fb >= K2_FILL) {
        // re-zero counters + descriptors for next replay (scan consumed them)
        int zb = fb - K2_FILL;
        if (zb == 0 && t < NB) { g_desc[0][t] = 0; g_desc[1][t] = 0; }
        int i = zb * 256 + t;
        if (i < NN)            g_cnt_st[i] = 0;
        else if (i < 2 * NN)   g_cnt_s[i - NN] = 0;
        return;
    }
    int i64 = g_i64sig - 1;
    int tt = fb * 256 + t;
    const int* ei; const int* off; const int* rank; int* csr; int g;
    if (tt < EE / 4)      { ei = ei_a; off = g_off_st; rank = g_rank_st; csr = g_csr_st; g = tt; }
    else if (tt < EE / 2) { ei = ei_b; off = g_off_s;  rank = g_rank_s;  csr = g_csr_s;  g = tt - EE / 4; }
    else return;
    int s0, s1, s2, s3, d0, d1, d2, d3;
    if (!i64) {
        int4 s = __ldg(&((const int4*)ei)[g]);
        int4 d = __ldg(&((const int4*)(ei + EE))[g]);
        s0 = s.x; s1 = s.y; s2 = s.z; s3 = s.w;
        d0 = d.x; d1 = d.y; d2 = d.z; d3 = d.w;
    } else {
        const int4* ps = (const int4*)ei;
        const int4* pd = (const int4*)(ei + 2 * EE);
        int4 sa = __ldg(&ps[2 * g]), sb = __ldg(&ps[2 * g + 1]);
        int4 da = __ldg(&pd[2 * g]), db = __ldg(&pd[2 * g + 1]);
        s0 = sa.x; s1 = sa.z; s2 = sb.x; s3 = sb.z;
        d0 = da.x; d1 = da.z; d2 = db.x; d3 = db.z;
    }
    int4 r = __ldg(&((const int4*)rank)[g]);
    if ((unsigned)d0 < NN && (unsigned)s0 < NN) csr[__ldg(&off[d0]) + r.x] = s0;
    if ((unsigned)d1 < NN && (unsigned)s1 < NN) csr[__ldg(&off[d1]) + r.y] = s1;
    if ((unsigned)d2 < NN && (unsigned)s2 < NN) csr[__ldg(&off[d2]) + r.z] = s2;
    if ((unsigned)d3 < NN && (unsigned)s3 < NN) csr[__ldg(&off[d3]) + r.w] = s3;
}

// ===== K3: agg + gemm(spin agg) + final(spin gemm) ===========================
#define TROW 80
#define TBYTES (128 * TROW)

__global__ void __launch_bounds__(256, 2) k_agf(
    const float* __restrict__ st_b, const float* __restrict__ s_b,
    const float* __restrict__ x_student, const float* __restrict__ x_studies,
    float* __restrict__ out)
{
    __shared__ __align__(16) unsigned char s_t[4][TBYTES];

    int bx = blockIdx.x;
    int tid = threadIdx.x;

    if (bx < K3_AGG) {
        // ---------- mean aggregation, warp per node ----------
        int type = bx >= 6250;
        int bb = bx - type * 6250;
        const int* off = type == 0 ? g_off_st : g_off_s;
        const int* csr = type == 0 ? g_csr_st : g_csr_s;
        const uint4* xs = (const uint4*)g_xh[type];
        int w = bb * 8 + (tid >> 5);      // always < NN (6250*8 == NN)
        int lane = tid & 31;
        int h = lane >> 4;
        int c = lane & 15;
        int beg = off[w], end = off[w + 1];
        int deg = end - beg;
        int nh = (deg - h + 1) >> 1;

        float acc[8];
#pragma unroll
        for (int i = 0; i < 8; i++) acc[i] = 0.f;

        int i = 0;
        int jb = beg + h;
        for (; i + 4 <= nh; i += 4) {
            int e0 = __ldg(&csr[jb + 2 * (i + 0)]);
            int e1 = __ldg(&csr[jb + 2 * (i + 1)]);
            int e2 = __ldg(&csr[jb + 2 * (i + 2)]);
            int e3 = __ldg(&csr[jb + 2 * (i + 3)]);
            uint4 v0 = __ldg(&xs[(long)e0 * 16 + c]);
            uint4 v1 = __ldg(&xs[(long)e1 * 16 + c]);
            uint4 v2 = __ldg(&xs[(long)e2 * 16 + c]);
            uint4 v3 = __ldg(&xs[(long)e3 * 16 + c]);
            acc_uint4(acc, v0); acc_uint4(acc, v1);
            acc_uint4(acc, v2); acc_uint4(acc, v3);
        }
        for (; i < nh; i++) {
            int e0 = __ldg(&csr[jb + 2 * i]);
            uint4 v0 = __ldg(&xs[(long)e0 * 16 + c]);
            acc_uint4(acc, v0);
        }
#pragma unroll
        for (int q = 0; q < 8; q++)
            acc[q] += __shfl_xor_sync(0xffffffffu, acc[q], 16);

        if (h == 0) {
            float inv = 1.0f / (float)(deg > 0 ? deg : 1);
            __nv_bfloat162 hi[4], lo[4];
#pragma unroll
            for (int q = 0; q < 4; q++)
                split_pair(acc[2 * q] * inv, acc[2 * q + 1] * inv, hi[q], lo[q]);
            int base = w * 64 + c * 4;
            *(uint4*)&g_Ahi[type][base] = *(uint4*)hi;
            *(uint4*)&g_Alo[type][base] = *(uint4*)lo;
        }
        block_signal(&g_agg_done);
        return;
    }

    if (bx < K3_AGG + K3_GEMM) {
        // ---------- HMMA GEMM with fused 128->2 projection epilogue ----------
        block_spin(&g_agg_done, K3_AGG);

        int gbi = bx - K3_AGG;
        int type = gbi >= NTILES;
        int bm = (gbi - type * NTILES) * 128;
        int t = tid;
        int wid = t >> 5, L = t & 31;
        int wm = wid & 3, wn = wid >> 2;

        const uint4* Ah4 = (const uint4*)g_Ahi[type];
        const uint4* Al4 = (const uint4*)g_Alo[type];
        const uint4* Bh4 = (const uint4*)g_Bhi[type];
        const uint4* Bl4 = (const uint4*)g_Blo[type];
        const float4* X4 = (const float4*)(type == 0 ? x_studies : x_student);
        const float* bias = type == 0 ? st_b : s_b;

        int lrow = t >> 1, lh = t & 1;
        int gm = bm + lrow;
        bool ok = gm < NN;
        long aoff = (long)gm * 16 + lh * 2;
        long xoff = (long)gm * 32 + lh * 4;
        int  boff = lrow * 32 + lh * 2;
        uint32_t sstore = (uint32_t)(lrow * TROW + lh * 32);
        const uint4 z4 = make_uint4(0, 0, 0, 0);
        uint32_t sb = smem_to_u32(s_t);

        uint32_t a_l = (uint32_t)((wm * 32 + (L & 7) + ((L >> 3) & 1) * 8) * TROW
                                  + (L >> 4) * 16);
        uint32_t b_l = (uint32_t)((wn * 64 + ((L >> 4)) * 8 + (L & 7)) * TROW
                                  + ((L >> 3) & 1) * 16);

        float acc[2][8][4];
#pragma unroll
        for (int i = 0; i < 2; i++)
#pragma unroll
            for (int j = 0; j < 8; j++)
#pragma unroll
                for (int q = 0; q < 4; q++) acc[i][j][q] = 0.f;

        for (int ci = 0; ci < 8; ci++) {
            __syncthreads();
            if (ci < 4) {
                uint4 v0 = ok ? __ldg(&Ah4[aoff + ci * 4]) : z4;
                uint4 v1 = ok ? __ldg(&Ah4[aoff + ci * 4 + 1]) : z4;
                *(uint4*)&s_t[0][sstore] = v0;  *(uint4*)&s_t[0][sstore + 16] = v1;
                v0 = ok ? __ldg(&Al4[aoff + ci * 4]) : z4;
                v1 = ok ? __ldg(&Al4[aoff + ci * 4 + 1]) : z4;
                *(uint4*)&s_t[1][sstore] = v0;  *(uint4*)&s_t[1][sstore + 16] = v1;
            } else {
                float f[16];
                long xb = xoff + (long)(ci - 4) * 8;
#pragma unroll
                for (int q = 0; q < 4; q++) {
                    float4 v = ok ? __ldg(&X4[xb + q]) : make_float4(0.f, 0.f, 0.f, 0.f);
                    f[q * 4 + 0] = v.x; f[q * 4 + 1] = v.y;
                    f[q * 4 + 2] = v.z; f[q * 4 + 3] = v.w;
                }
                __nv_bfloat162 hi[8], lo[8];
#pragma unroll
                for (int q = 0; q < 8; q++)
                    split_pair(f[2 * q], f[2 * q + 1], hi[q], lo[q]);
                *(uint4*)&s_t[0][sstore]      = *(uint4*)&hi[0];
                *(uint4*)&s_t[0][sstore + 16] = *(uint4*)&hi[4];
                *(uint4*)&s_t[1][sstore]      = *(uint4*)&lo[0];
                *(uint4*)&s_t[1][sstore + 16] = *(uint4*)&lo[4];
            }
            {
                uint4 v0 = __ldg(&Bh4[boff + ci * 4]);
                uint4 v1 = __ldg(&Bh4[boff + ci * 4 + 1]);
                *(uint4*)&s_t[2][sstore] = v0;  *(uint4*)&s_t[2][sstore + 16] = v1;
                v0 = __ldg(&Bl4[boff + ci * 4]);
                v1 = __ldg(&Bl4[boff + ci * 4 + 1]);
                *(uint4*)&s_t[3][sstore] = v0;  *(uint4*)&s_t[3][sstore + 16] = v1;
            }
            __syncthreads();

#pragma unroll
            for (int k0 = 0; k0 < 2; k0++) {
                uint32_t koff = (uint32_t)(k0 * 32);
                uint32_t ah[2][4], al[2][4], b[4][4];
                ldsm4(ah[0], sb + 0 * TBYTES + a_l + koff);
                ldsm4(ah[1], sb + 0 * TBYTES + a_l + 16 * TROW + koff);
                ldsm4(al[0], sb + 1 * TBYTES + a_l + koff);
                ldsm4(al[1], sb + 1 * TBYTES + a_l + 16 * TROW + koff);
#pragma unroll
                for (int p = 0; p < 4; p++)
                    ldsm4(b[p], sb + 2 * TBYTES + b_l + p * 16 * TROW + koff);
#pragma unroll
                for (int i = 0; i < 2; i++)
#pragma unroll
                    for (int j = 0; j < 8; j++) {
                        mma16816(acc[i][j], ah[i], &b[j >> 1][(j & 1) * 2]);
                        mma16816(acc[i][j], al[i], &b[j >> 1][(j & 1) * 2]);
                    }
#pragma unroll
                for (int p = 0; p < 4; p++)
                    ldsm4(b[p], sb + 3 * TBYTES + b_l + p * 16 * TROW + koff);
#pragma unroll
                for (int i = 0; i < 2; i++)
#pragma unroll
                    for (int j = 0; j < 8; j++)
                        mma16816(acc[i][j], ah[i], &b[j >> 1][(j & 1) * 2]);
            }
        }

        // fused projection epilogue: v = relu(h + bias) @ [w0|w1]
        const float* w0v = type ? g_wl0 : g_wr0;
        const float* w1v = type ? g_wl1 : g_wr1;
        float2* dst = type ? g_p : g_q;

        float pp[8];
#pragma unroll
        for (int q = 0; q < 8; q++) pp[q] = 0.f;
#pragma unroll
        for (int i = 0; i < 2; i++)
#pragma unroll
            for (int j = 0; j < 8; j++) {
                int col = wn * 64 + j * 8 + (L & 3) * 2;
                float b0 = bias[col], b1 = bias[col + 1];
                float w00 = w0v[col], w01 = w0v[col + 1];
                float w10 = w1v[col], w11 = w1v[col + 1];
                float ox = fmaxf(acc[i][j][0] + b0, 0.f);
                float oy = fmaxf(acc[i][j][1] + b1, 0.f);
                pp[i * 4 + 0] += ox * w00 + oy * w01;
                pp[i * 4 + 1] += ox * w10 + oy * w11;
                ox = fmaxf(acc[i][j][2] + b0, 0.f);
                oy = fmaxf(acc[i][j][3] + b1, 0.f);
                pp[i * 4 + 2] += ox * w00 + oy * w01;
                pp[i * 4 + 3] += ox * w10 + oy * w11;
            }
#pragma unroll
        for (int o = 1; o <= 2; o <<= 1)
#pragma unroll
            for (int q = 0; q < 8; q++)
                pp[q] += __shfl_xor_sync(0xffffffffu, pp[q], o);

        __syncthreads();
        float* ps = (float*)s_t;
        if ((L & 3) == 0) {
            int lr = wm * 32 + (L >> 2);
#pragma unroll
            for (int i = 0; i < 2; i++)
#pragma unroll
                for (int r = 0; r < 2; r++) {
                    int row = lr + i * 16 + r * 8;
                    ps[(row * 2 + wn) * 2 + 0] = pp[i * 4 + r * 2 + 0];
                    ps[(row * 2 + wn) * 2 + 1] = pp[i * 4 + r * 2 + 1];
                }
        }
        __syncthreads();
        if (t < 128) {
            int gr = bm + t;
            if (gr < NN) {
                float a0 = ps[(t * 2 + 0) * 2 + 0] + ps[(t * 2 + 1) * 2 + 0];
                float a1 = ps[(t * 2 + 0) * 2 + 1] + ps[(t * 2 + 1) * 2 + 1];
                dst[gr] = make_float2(a0, a1);
            }
        }
        block_signal(&g_gemm_done);
        return;
    }

    // ---------- final: out = agg(p)/deg + q + b' ----------
    block_spin(&g_gemm_done, K3_GEMM);
    {
        int fb = bx - K3_AGG - K3_GEMM;
        int w = fb * 8 + (tid >> 5);     // always < NN
        int lane = tid & 31;
        int beg = g_off_st[w], end = g_off_st[w + 1];
        float e0 = 0.f, e1 = 0.f;
        for (int j = beg + lane; j < end; j += 32) {
            int s = __ldg(&g_csr_st[j]);
            float2 pv = g_p[s];
            e0 += pv.x; e1 += pv.y;
        }
        for (int o = 16; o; o >>= 1) {
            e0 += __shfl_xor_sync(0xffffffffu, e0, o);
            e1 += __shfl_xor_sync(0xffffffffu, e1, o);
        }
        if (lane == 0) {
            int deg = end - beg;
            float inv = 1.0f / (float)(deg > 0 ? deg : 1);
            float2 q = g_q[w];
            out[w * 2]     = e0 * inv + q.x + g_b2[0];
            out[w * 2 + 1] = e1 * inv + q.y + g_b2[1];
        }
    }
}

// ---------------- launch ------------------------------------------------------
extern "C" void kernel_launch(void* const* d_in, const int* in_sizes, int n_in,
                              void* d_out, int out_size)
{
    const float* x_student   = (const float*)d_in[0];
    const float* x_studies   = (const float*)d_in[1];
    const int*   ei_s2st     = (const int*)d_in[2];
    const int*   ei_st2s     = (const int*)d_in[3];
    const float* l1_st_Wl = (const float*)d_in[4];
    const float* l1_st_b  = (const float*)d_in[5];
    const float* l1_st_Wr = (const float*)d_in[6];
    const float* l1_s_Wl  = (const float*)d_in[7];
    const float* l1_s_b   = (const float*)d_in[8];
    const float* l1_s_Wr  = (const float*)d_in[9];
    const float* l2_st_Wl = (const float*)d_in[10];
    const float* l2_st_b  = (const float*)d_in[11];
    const float* l2_st_Wr = (const float*)d_in[12];
    const float* lin_W    = (const float*)d_in[16];
    const float* lin_b    = (const float*)d_in[17];
    float* out = (float*)d_out;

    k_pc<<<K1_TOTAL, 256>>>(x_student, x_studies, ei_s2st, ei_st2s,
                            l1_st_Wl, l1_st_Wr, l1_s_Wl, l1_s_Wr,
                            l2_st_Wl, l2_st_b, l2_st_Wr, lin_W, lin_b);

    k_sf<<<K2_TOTAL, 256>>>(ei_s2st, ei_st2s);

    k_agf<<<K3_TOTAL, 256>>>(l1_st_b, l1_s_b, x_student, x_studies, out);
}

// round 12
// speedup vs baseline: 1.4556x; 1.4556x over previous
#include <cuda_runtime.h>
#include <cuda_bf16.h>
#include <cstdint>

#define NN 50000
#define EE 1600000
#define DD 128
#define NB 196          // ceil(NN / 256)
#define NTILES 391      // ceil(NN / 128)

// merged count+wprep block ranges (conv eliminated: agg gathers fp32 directly)
#define PC_COUNT 3125                    // EE/2 threads / 256
#define PC_WPREP 65
#define PC_TOTAL (PC_COUNT + PC_WPREP)
// fill kernel: 3125 fill blocks + 391 zero blocks (re-zero for next replay)
#define FB_FILL 3125
#define FB_ZERO 391

// ---------------- scratch (device globals; no allocation allowed) ----------
// Zero-initialized at module load; k_fill restores the zero-invariant on
// g_cnt_* / g_desc every call, so every graph replay sees zeroed counters.
__device__ float2 g_p[NN];        // relu(h_s)  @ Wl'  (type 1 epilogue)
__device__ float2 g_q[NN];        // relu(h_st) @ Wr'  (type 0 epilogue)
__device__ int g_csr_st[EE];
__device__ int g_csr_s [EE];
__device__ int g_rank_st[EE];     // edge rank within its dst (from count)
__device__ int g_rank_s [EE];
__device__ int g_cnt_st[NN];
__device__ int g_cnt_s [NN];
__device__ int g_off_st[NN + 1];
__device__ int g_off_s [NN + 1];
__device__ int g_desc[2][NB];     // lookback descriptors: 0=not ready, else agg+1
__device__ float g_wl0[DD], g_wl1[DD], g_wr0[DD], g_wr1[DD], g_b2[2];
__device__ int g_i64;

// A mean-part only, bf16 hi/lo pairs: [type][node*64 + pair]  (128 bf16/row)
__device__ __nv_bfloat162 g_Ahi[2][NN * 64];
__device__ __nv_bfloat162 g_Alo[2][NN * 64];
// B^T = [Wl;Wr]^T per type: [type][n*128 + pair]
__device__ __nv_bfloat162 g_Bhi[2][128 * 128];
__device__ __nv_bfloat162 g_Blo[2][128 * 128];

// ================= helpers ====================================================
__device__ __forceinline__ uint32_t smem_to_u32(const void* p) {
    uint32_t a;
    asm("{ .reg .u64 t; cvta.to.shared.u64 t, %1; cvt.u32.u64 %0, t; }"
        : "=r"(a) : "l"(p));
    return a;
}
__device__ __forceinline__ void ldsm4(uint32_t* r, uint32_t addr) {
    asm volatile("ldmatrix.sync.aligned.m8n8.x4.shared.b16 {%0,%1,%2,%3}, [%4];"
        : "=r"(r[0]), "=r"(r[1]), "=r"(r[2]), "=r"(r[3]) : "r"(addr));
}
__device__ __forceinline__ void mma16816(float* c, const uint32_t* a, const uint32_t* b) {
    asm volatile("mma.sync.aligned.m16n8k16.row.col.f32.bf16.bf16.f32 "
        "{%0,%1,%2,%3}, {%4,%5,%6,%7}, {%8,%9}, {%0,%1,%2,%3};"
        : "+f"(c[0]), "+f"(c[1]), "+f"(c[2]), "+f"(c[3])
        : "r"(a[0]), "r"(a[1]), "r"(a[2]), "r"(a[3]), "r"(b[0]), "r"(b[1]));
}
__device__ __forceinline__ void split_pair(float a, float b,
                                           __nv_bfloat162& hi, __nv_bfloat162& lo)
{
    __nv_bfloat16 ha = __float2bfloat16(a), hb = __float2bfloat16(b);
    hi.x = ha; hi.y = hb;
    lo.x = __float2bfloat16(a - __bfloat162float(ha));
    lo.y = __float2bfloat16(b - __bfloat162float(hb));
}

// ---------------- probe: int64 vs int32 edge-index layout (1 block) ----------
__global__ void k_probe(const int* __restrict__ ei)
{
    __shared__ int any_nonzero;
    if (threadIdx.x == 0) any_nonzero = 0;
    __syncthreads();
    if (ei[2 * threadIdx.x + 1] != 0) atomicOr(&any_nonzero, 1);
    __syncthreads();
    if (threadIdx.x == 0) g_i64 = any_nonzero ? 0 : 1;
}

// ===== merged count + wprep ===================================================
__global__ void k_prepcount(
    const int* __restrict__ ei_a, const int* __restrict__ ei_b,
    const float* __restrict__ st_Wl, const float* __restrict__ st_Wr,
    const float* __restrict__ s_Wl,  const float* __restrict__ s_Wr,
    const float* __restrict__ Wl2, const float* __restrict__ b2,
    const float* __restrict__ Wr2, const float* __restrict__ linW,
    const float* __restrict__ linb)
{
    int bx = blockIdx.x;
    int tid = threadIdx.x;

    if (bx < PC_COUNT) {
        // ---- histogram + rank capture: 4 edges/thread, int4 ----
        int i64 = g_i64;
        int t = bx * 256 + tid;
        const int* ei; int* cnt; int* rank; int g;
        if (t < EE / 4)      { ei = ei_a; cnt = g_cnt_st; rank = g_rank_st; g = t; }
        else if (t < EE / 2) { ei = ei_b; cnt = g_cnt_s;  rank = g_rank_s;  g = t - EE / 4; }
        else return;
        int d0, d1, d2, d3;
        if (!i64) {
            int4 d = __ldg(&((const int4*)(ei + EE))[g]);
            d0 = d.x; d1 = d.y; d2 = d.z; d3 = d.w;
        } else {
            const int4* p = (const int4*)(ei + 2 * EE);
            int4 a = __ldg(&p[2 * g]), b = __ldg(&p[2 * g + 1]);
            d0 = a.x; d1 = a.z; d2 = b.x; d3 = b.z;
        }
        int4 r = make_int4(0, 0, 0, 0);
        if ((unsigned)d0 < NN) r.x = atomicAdd(&cnt[d0], 1);
        if ((unsigned)d1 < NN) r.y = atomicAdd(&cnt[d1], 1);
        if ((unsigned)d2 < NN) r.z = atomicAdd(&cnt[d2], 1);
        if ((unsigned)d3 < NN) r.w = atomicAdd(&cnt[d3], 1);
        ((int4*)rank)[g] = r;
        return;
    }
    // ---- weight prep ----
    int wb = bx - PC_COUNT;
    if (wb == 64) {
        int k = tid >> 1, j = tid & 1;
        float sl = 0.f, sr = 0.f;
        for (int m = 0; m < 128; m++) {
            float w = linW[m * 2 + j];
            sl += Wl2[k * 128 + m] * w;
            sr += Wr2[k * 128 + m] * w;
        }
        if (j == 0) { g_wl0[k] = sl; g_wr0[k] = sr; }
        else        { g_wl1[k] = sl; g_wr1[k] = sr; }
        if (k == 0) {
            float sb = 0.f;
            for (int m = 0; m < 128; m++) sb += b2[m] * linW[m * 2 + j];
            g_b2[j] = sb + linb[j];
        }
        return;
    }
    int t = wb * 256 + tid;   // [type][n][k4]
    int k4 = t & 63, n = (t >> 6) & 127, type = t >> 13;
    const float* Wl = type == 0 ? st_Wl : s_Wl;
    const float* Wr = type == 0 ? st_Wr : s_Wr;
    int k = k4 * 4;
    float v[4];
#pragma unroll
    for (int i = 0; i < 4; i++) {
        int kk = k + i;
        v[i] = (kk < 128) ? Wl[kk * 128 + n] : Wr[(kk - 128) * 128 + n];
    }
    __nv_bfloat162 h0, l0, h1, l1;
    split_pair(v[0], v[1], h0, l0);
    split_pair(v[2], v[3], h1, l1);
    int base = n * 128 + k4 * 2;
    g_Bhi[type][base] = h0;     g_Bhi[type][base + 1] = h1;
    g_Blo[type][base] = l0;     g_Blo[type][base + 1] = l1;
}

// --------- single-kernel exclusive scan (all blocks co-resident) -------------
__global__ void k_scan()
{
    int y = blockIdx.y, b = blockIdx.x;
    const int* cnt = y ? g_cnt_s : g_cnt_st;
    int* off = y ? g_off_s : g_off_st;
    int t = threadIdx.x;
    int i = b * 256 + t;
    int v = (i < NN) ? cnt[i] : 0;
    __shared__ int sh[256];
    sh[t] = v;
    __syncthreads();
#pragma unroll
    for (int o = 1; o < 256; o <<= 1) {
        int u = (t >= o) ? sh[t - o] : 0;
        __syncthreads();
        sh[t] += u;
        __syncthreads();
    }
    int incl = sh[t];
    if (t == 255) atomicExch(&g_desc[y][b], incl + 1);   // publish aggregate+1

    int partial = 0;
    if (t < b) {
        int d;
        do { d = atomicAdd(&g_desc[y][t], 0); } while (d == 0);
        partial = d - 1;
    }
    __syncthreads();
    sh[t] = partial;
    __syncthreads();
#pragma unroll
    for (int o = 128; o; o >>= 1) {
        if (t < o) sh[t] += sh[t + o];
        __syncthreads();
    }
    int excl = sh[0] + incl - v;
    if (i < NN) {
        off[i] = excl;
        if (i == NN - 1) off[NN] = excl + v;
    }
}

// --------- CSR fill (atomic-free) + counter re-zero for next replay ----------
__global__ void k_fill(const int* __restrict__ ei_a, const int* __restrict__ ei_b)
{
    int bx = blockIdx.x;
    int tid = threadIdx.x;
    if (bx >= FB_FILL) {
        int zb = bx - FB_FILL;
        if (zb == 0 && tid < NB) { g_desc[0][tid] = 0; g_desc[1][tid] = 0; }
        int i = zb * 256 + tid;
        if (i < NN)            g_cnt_st[i] = 0;
        else if (i < 2 * NN)   g_cnt_s[i - NN] = 0;
        return;
    }
    int i64 = g_i64;
    int t = bx * 256 + tid;
    const int* ei; const int* off; const int* rank; int* csr; int g;
    if (t < EE / 4)      { ei = ei_a; off = g_off_st; rank = g_rank_st; csr = g_csr_st; g = t; }
    else if (t < EE / 2) { ei = ei_b; off = g_off_s;  rank = g_rank_s;  csr = g_csr_s;  g = t - EE / 4; }
    else return;
    int s0, s1, s2, s3, d0, d1, d2, d3;
    if (!i64) {
        int4 s = __ldg(&((const int4*)ei)[g]);
        int4 d = __ldg(&((const int4*)(ei + EE))[g]);
        s0 = s.x; s1 = s.y; s2 = s.z; s3 = s.w;
        d0 = d.x; d1 = d.y; d2 = d.z; d3 = d.w;
    } else {
        const int4* ps = (const int4*)ei;
        const int4* pd = (const int4*)(ei + 2 * EE);
        int4 sa = __ldg(&ps[2 * g]), sb = __ldg(&ps[2 * g + 1]);
        int4 da = __ldg(&pd[2 * g]), db = __ldg(&pd[2 * g + 1]);
        s0 = sa.x; s1 = sa.z; s2 = sb.x; s3 = sb.z;
        d0 = da.x; d1 = da.z; d2 = db.x; d3 = db.z;
    }
    int4 r = __ldg(&((const int4*)rank)[g]);
    if ((unsigned)d0 < NN && (unsigned)s0 < NN) csr[__ldg(&off[d0]) + r.x] = s0;
    if ((unsigned)d1 < NN && (unsigned)s1 < NN) csr[__ldg(&off[d1]) + r.y] = s1;
    if ((unsigned)d2 < NN && (unsigned)s2 < NN) csr[__ldg(&off[d2]) + r.z] = s2;
    if ((unsigned)d3 < NN && (unsigned)s3 < NN) csr[__ldg(&off[d3]) + r.w] = s3;
}

// ---- mean aggregation over fp32 inputs, warp per node, half-warp per edge ---
// fp32 row = 512B; half-warp lane c loads float4 at [e*32+c] and [e*32+16+c].
__global__ void k_agg(const float* __restrict__ x_student,
                      const float* __restrict__ x_studies)
{
    int type = blockIdx.y;
    const int* off = type == 0 ? g_off_st : g_off_s;
    const int* csr = type == 0 ? g_csr_st : g_csr_s;
    const float4* xs = (const float4*)(type == 0 ? x_student : x_studies);
    int w = (blockIdx.x * blockDim.x + threadIdx.x) >> 5;
    int lane = threadIdx.x & 31;
    if (w >= NN) return;
    int h = lane >> 4;
    int c = lane & 15;
    int beg = off[w], end = off[w + 1];
    int deg = end - beg;
    int nh = (deg - h + 1) >> 1;

    float acc[8];
#pragma unroll
    for (int i = 0; i < 8; i++) acc[i] = 0.f;

    int i = 0;
    int jb = beg + h;
    for (; i + 2 <= nh; i += 2) {
        int e0 = __ldg(&csr[jb + 2 * (i + 0)]);
        int e1 = __ldg(&csr[jb + 2 * (i + 1)]);
        float4 a0 = __ldg(&xs[(long)e0 * 32 + c]);
        float4 a1 = __ldg(&xs[(long)e0 * 32 + 16 + c]);
        float4 b0 = __ldg(&xs[(long)e1 * 32 + c]);
        float4 b1 = __ldg(&xs[(long)e1 * 32 + 16 + c]);
        acc[0] += a0.x + b0.x; acc[1] += a0.y + b0.y;
        acc[2] += a0.z + b0.z; acc[3] += a0.w + b0.w;
        acc[4] += a1.x + b1.x; acc[5] += a1.y + b1.y;
        acc[6] += a1.z + b1.z; acc[7] += a1.w + b1.w;
    }
    if (i < nh) {
        int e0 = __ldg(&csr[jb + 2 * i]);
        float4 a0 = __ldg(&xs[(long)e0 * 32 + c]);
        float4 a1 = __ldg(&xs[(long)e0 * 32 + 16 + c]);
        acc[0] += a0.x; acc[1] += a0.y; acc[2] += a0.z; acc[3] += a0.w;
        acc[4] += a1.x; acc[5] += a1.y; acc[6] += a1.z; acc[7] += a1.w;
    }

#pragma unroll
    for (int q = 0; q < 8; q++)
        acc[q] += __shfl_xor_sync(0xffffffffu, acc[q], 16);

    if (h == 0) {
        float inv = 1.0f / (float)(deg > 0 ? deg : 1);
        __nv_bfloat162 hi[4], lo[4];
        split_pair(acc[0] * inv, acc[1] * inv, hi[0], lo[0]);
        split_pair(acc[2] * inv, acc[3] * inv, hi[1], lo[1]);
        split_pair(acc[4] * inv, acc[5] * inv, hi[2], lo[2]);
        split_pair(acc[6] * inv, acc[7] * inv, hi[3], lo[3]);
        // lane c: features c*4..c*4+3 -> pairs w*64 + c*2 (+1)
        //         features 64+c*4..  -> pairs w*64 + 32 + c*2 (+1)
        int base = w * 64 + c * 2;
        *(uint2*)&g_Ahi[type][base]      = *(uint2*)&hi[0];
        *(uint2*)&g_Ahi[type][base + 32] = *(uint2*)&hi[2];
        *(uint2*)&g_Alo[type][base]      = *(uint2*)&lo[0];
        *(uint2*)&g_Alo[type][base + 32] = *(uint2*)&lo[2];
    }
}

// ======= HMMA layer-1 GEMM with fused 128->2 projection epilogue =============
// A k-chunks 0-3: mean (bf16 hi/lo from g_A*); chunks 4-7: raw x loaded as
// fp32 and split to hi/lo in registers.
// type 0: q = relu(h_st) @ [wr0|wr1] -> g_q
// type 1: p = relu(h_s)  @ [wl0|wl1] -> g_p
#define TROW 80
#define TBYTES (128 * TROW)

__global__ void __launch_bounds__(256, 2) k_gemm_mma(
    const float* __restrict__ st_b, const float* __restrict__ s_b,
    const float* __restrict__ x_student, const float* __restrict__ x_studies)
{
    __shared__ __align__(16) unsigned char s_t[4][TBYTES];   // Ah, Al, Bh, Bl

    int t = threadIdx.x;
    int type = blockIdx.y;
    int bm = blockIdx.x * 128;
    int wid = t >> 5, L = t & 31;
    int wm = wid & 3, wn = wid >> 2;

    const uint4* Ah4 = (const uint4*)g_Ahi[type];
    const uint4* Al4 = (const uint4*)g_Alo[type];
    const uint4* Bh4 = (const uint4*)g_Bhi[type];
    const uint4* Bl4 = (const uint4*)g_Blo[type];
    const float4* X4 = (const float4*)(type == 0 ? x_studies : x_student);
    const float* bias = type == 0 ? st_b : s_b;

    int lrow = t >> 1, lh = t & 1;
    int gm = bm + lrow;
    bool ok = gm < NN;
    long aoff = (long)gm * 16 + lh * 2;       // mean A: 16 uint4/row
    long xoff = (long)gm * 32 + lh * 4;       // x fp32: 32 float4/row
    int  boff = lrow * 32 + lh * 2;
    uint32_t sstore = (uint32_t)(lrow * TROW + lh * 32);
    const uint4 z4 = make_uint4(0, 0, 0, 0);

    uint32_t sb = smem_to_u32(s_t);

    uint32_t a_l = (uint32_t)((wm * 32 + (L & 7) + ((L >> 3) & 1) * 8) * TROW
                              + (L >> 4) * 16);
    uint32_t b_l = (uint32_t)((wn * 64 + ((L >> 4)) * 8 + (L & 7)) * TROW
                              + ((L >> 3) & 1) * 16);

    float acc[2][8][4];
#pragma unroll
    for (int i = 0; i < 2; i++)
#pragma unroll
        for (int j = 0; j < 8; j++)
#pragma unroll
            for (int q = 0; q < 4; q++) acc[i][j][q] = 0.f;

    for (int ci = 0; ci < 8; ci++) {
        __syncthreads();
        if (ci < 4) {
            uint4 v0 = ok ? __ldg(&Ah4[aoff + ci * 4]) : z4;
            uint4 v1 = ok ? __ldg(&Ah4[aoff + ci * 4 + 1]) : z4;
            *(uint4*)&s_t[0][sstore] = v0;  *(uint4*)&s_t[0][sstore + 16] = v1;
            v0 = ok ? __ldg(&Al4[aoff + ci * 4]) : z4;
            v1 = ok ? __ldg(&Al4[aoff + ci * 4 + 1]) : z4;
            *(uint4*)&s_t[1][sstore] = v0;  *(uint4*)&s_t[1][sstore + 16] = v1;
        } else {
            float f[16];
            long xb = xoff + (long)(ci - 4) * 8;
#pragma unroll
            for (int q = 0; q < 4; q++) {
                float4 v = ok ? __ldg(&X4[xb + q]) : make_float4(0.f, 0.f, 0.f, 0.f);
                f[q * 4 + 0] = v.x; f[q * 4 + 1] = v.y;
                f[q * 4 + 2] = v.z; f[q * 4 + 3] = v.w;
            }
            __nv_bfloat162 hi[8], lo[8];
#pragma unroll
            for (int q = 0; q < 8; q++)
                split_pair(f[2 * q], f[2 * q + 1], hi[q], lo[q]);
            *(uint4*)&s_t[0][sstore]      = *(uint4*)&hi[0];
            *(uint4*)&s_t[0][sstore + 16] = *(uint4*)&hi[4];
            *(uint4*)&s_t[1][sstore]      = *(uint4*)&lo[0];
            *(uint4*)&s_t[1][sstore + 16] = *(uint4*)&lo[4];
        }
        {
            uint4 v0 = __ldg(&Bh4[boff + ci * 4]);
            uint4 v1 = __ldg(&Bh4[boff + ci * 4 + 1]);
            *(uint4*)&s_t[2][sstore] = v0;  *(uint4*)&s_t[2][sstore + 16] = v1;
            v0 = __ldg(&Bl4[boff + ci * 4]);
            v1 = __ldg(&Bl4[boff + ci * 4 + 1]);
            *(uint4*)&s_t[3][sstore] = v0;  *(uint4*)&s_t[3][sstore + 16] = v1;
        }
        __syncthreads();

#pragma unroll
        for (int k0 = 0; k0 < 2; k0++) {
            uint32_t koff = (uint32_t)(k0 * 32);
            uint32_t ah[2][4], al[2][4], b[4][4];
            ldsm4(ah[0], sb + 0 * TBYTES + a_l + koff);
            ldsm4(ah[1], sb + 0 * TBYTES + a_l + 16 * TROW + koff);
            ldsm4(al[0], sb + 1 * TBYTES + a_l + koff);
            ldsm4(al[1], sb + 1 * TBYTES + a_l + 16 * TROW + koff);
#pragma unroll
            for (int p = 0; p < 4; p++)
                ldsm4(b[p], sb + 2 * TBYTES + b_l + p * 16 * TROW + koff);
#pragma unroll
            for (int i = 0; i < 2; i++)
#pragma unroll
                for (int j = 0; j < 8; j++) {
                    mma16816(acc[i][j], ah[i], &b[j >> 1][(j & 1) * 2]);
                    mma16816(acc[i][j], al[i], &b[j >> 1][(j & 1) * 2]);
                }
#pragma unroll
            for (int p = 0; p < 4; p++)
                ldsm4(b[p], sb + 3 * TBYTES + b_l + p * 16 * TROW + koff);
#pragma unroll
            for (int i = 0; i < 2; i++)
#pragma unroll
                for (int j = 0; j < 8; j++)
                    mma16816(acc[i][j], ah[i], &b[j >> 1][(j & 1) * 2]);
        }
    }

    // unified fused projection epilogue: v = relu(h + bias) @ [w0|w1]
    {
        const float* w0v = type ? g_wl0 : g_wr0;
        const float* w1v = type ? g_wl1 : g_wr1;
        float2* dst = type ? g_p : g_q;

        float pp[8];
#pragma unroll
        for (int q = 0; q < 8; q++) pp[q] = 0.f;
#pragma unroll
        for (int i = 0; i < 2; i++)
#pragma unroll
            for (int j = 0; j < 8; j++) {
                int col = wn * 64 + j * 8 + (L & 3) * 2;
                float b0 = bias[col], b1 = bias[col + 1];
                float w00 = w0v[col], w01 = w0v[col + 1];
                float w10 = w1v[col], w11 = w1v[col + 1];
                float ox = fmaxf(acc[i][j][0] + b0, 0.f);
                float oy = fmaxf(acc[i][j][1] + b1, 0.f);
                pp[i * 4 + 0] += ox * w00 + oy * w01;
                pp[i * 4 + 1] += ox * w10 + oy * w11;
                ox = fmaxf(acc[i][j][2] + b0, 0.f);
                oy = fmaxf(acc[i][j][3] + b1, 0.f);
                pp[i * 4 + 2] += ox * w00 + oy * w01;
                pp[i * 4 + 3] += ox * w10 + oy * w11;
            }
#pragma unroll
        for (int o = 1; o <= 2; o <<= 1)
#pragma unroll
            for (int q = 0; q < 8; q++)
                pp[q] += __shfl_xor_sync(0xffffffffu, pp[q], o);

        __syncthreads();                      // s_t no longer read by MMAs
        float* ps = (float*)s_t;              // [row][wn][2] = 2KB
        if ((L & 3) == 0) {
            int lr = wm * 32 + (L >> 2);
#pragma unroll
            for (int i = 0; i < 2; i++)
#pragma unroll
                for (int r = 0; r < 2; r++) {
                    int row = lr + i * 16 + r * 8;
                    ps[(row * 2 + wn) * 2 + 0] = pp[i * 4 + r * 2 + 0];
                    ps[(row * 2 + wn) * 2 + 1] = pp[i * 4 + r * 2 + 1];
                }
        }
        __syncthreads();
        if (t < 128) {
            int gr = bm + t;
            if (gr < NN) {
                float a0 = ps[(t * 2 + 0) * 2 + 0] + ps[(t * 2 + 1) * 2 + 0];
                float a1 = ps[(t * 2 + 0) * 2 + 1] + ps[(t * 2 + 1) * 2 + 1];
                dst[gr] = make_float2(a0, a1);
            }
        }
    }
}

// ------- out = agg(p)/deg + q + b' — warp per node ----------------------------
__global__ void k_final(float* __restrict__ out)
{
    int w = (blockIdx.x * blockDim.x + threadIdx.x) >> 5;
    int lane = threadIdx.x & 31;
    if (w >= NN) return;
    int beg = g_off_st[w], end = g_off_st[w + 1];
    float e0 = 0.f, e1 = 0.f;
    for (int j = beg + lane; j < end; j += 32) {
        int s = __ldg(&g_csr_st[j]);
        float2 pv = g_p[s];
        e0 += pv.x; e1 += pv.y;
    }
    for (int o = 16; o; o >>= 1) {
        e0 += __shfl_xor_sync(0xffffffffu, e0, o);
        e1 += __shfl_xor_sync(0xffffffffu, e1, o);
    }
    if (lane == 0) {
        int deg = end - beg;
        float inv = 1.0f / (float)(deg > 0 ? deg : 1);
        float2 q = g_q[w];
        out[w * 2]     = e0 * inv + q.x + g_b2[0];
        out[w * 2 + 1] = e1 * inv + q.y + g_b2[1];
    }
}

// ---------------- launch ------------------------------------------------------
extern "C" void kernel_launch(void* const* d_in, const int* in_sizes, int n_in,
                              void* d_out, int out_size)
{
    const float* x_student   = (const float*)d_in[0];
    const float* x_studies   = (const float*)d_in[1];
    const int*   ei_s2st     = (const int*)d_in[2];
    const int*   ei_st2s     = (const int*)d_in[3];
    const float* l1_st_Wl = (const float*)d_in[4];
    const float* l1_st_b  = (const float*)d_in[5];
    const float* l1_st_Wr = (const float*)d_in[6];
    const float* l1_s_Wl  = (const float*)d_in[7];
    const float* l1_s_b   = (const float*)d_in[8];
    const float* l1_s_Wr  = (const float*)d_in[9];
    const float* l2_st_Wl = (const float*)d_in[10];
    const float* l2_st_b  = (const float*)d_in[11];
    const float* l2_st_Wr = (const float*)d_in[12];
    const float* lin_W    = (const float*)d_in[16];
    const float* lin_b    = (const float*)d_in[17];
    float* out = (float*)d_out;

    k_probe<<<1, 512>>>(ei_s2st);

    k_prepcount<<<PC_TOTAL, 256>>>(ei_s2st, ei_st2s,
                                   l1_st_Wl, l1_st_Wr, l1_s_Wl, l1_s_Wr,
                                   l2_st_Wl, l2_st_b, l2_st_Wr, lin_W, lin_b);

    dim3 gs(NB, 2);
    k_scan<<<gs, 256>>>();

    k_fill<<<FB_FILL + FB_ZERO, 256>>>(ei_s2st, ei_st2s);   // capture slot

    dim3 ga((NN + 7) / 8, 2);
    k_agg<<<ga, 256>>>(x_student, x_studies);

    dim3 gg(NTILES, 2);
    k_gemm_mma<<<gg, 256>>>(l1_st_b, l1_s_b, x_student, x_studies);

    k_final<<<(NN + 7) / 8, 256>>>(out);
}